// round 14
// baseline (speedup 1.0000x reference)
#include <cuda_runtime.h>
#include <cuda_fp16.h>
#include <cstdint>

// ---------------------------------------------------------------------------
// Problem constants
// ---------------------------------------------------------------------------
#define Bn     32
#define Nn     2048
#define PDn    2
#define LATn   128
#define Hn     256
#define STEPSn 5
#define DINn   131
#define NPTS   (Bn * Nn)         // 65536
#define PPC    128               // points per CTA (= GEMM M)
#define NCTA   (NPTS / PPC)      // 512
#define KCH    64                // K-chunk
#define NCHUNK (Hn / KCH)        // 4
#define NTHREADS 512
#define NTILES (STEPSn * 2 * NCHUNK)   // 40 B-tiles over the whole kernel

// ---------------------------------------------------------------------------
// Device globals
// ---------------------------------------------------------------------------
// fp16 weights, chunk-major: [matrix(2: W2, M)][chunk(4)][j=256][kk=64]
__device__ __align__(16) __half g_W16[2 * NCHUNK * Hn * KCH];
__device__ __align__(16) float g_base[Bn * Hn];
__device__ __align__(16) float g_c0[Hn], g_c1[Hn], g_ct[Hn], g_csum[Hn];

__device__ __forceinline__ float ftanh(float x) {
    float e = __expf(2.0f * x);
    return 1.0f - __fdividef(2.0f, e + 1.0f);
}
__device__ __forceinline__ uint32_t smem_u32(const void* p) {
    uint32_t a;
    asm("{ .reg .u64 t; cvta.to.shared.u64 t, %1; cvt.u32.u64 %0, t; }"
        : "=r"(a) : "l"(p));
    return a;
}
__device__ __forceinline__ void ldsm4(uint32_t& r0, uint32_t& r1,
                                      uint32_t& r2, uint32_t& r3, uint32_t addr) {
    asm volatile("ldmatrix.sync.aligned.m8n8.x4.shared.b16 {%0,%1,%2,%3}, [%4];"
                 : "=r"(r0), "=r"(r1), "=r"(r2), "=r"(r3) : "r"(addr));
}
__device__ __forceinline__ void mma16816(float* d, const uint32_t* a,
                                         uint32_t b0, uint32_t b1) {
    asm volatile(
        "mma.sync.aligned.m16n8k16.row.col.f32.f16.f16.f32 "
        "{%0,%1,%2,%3},{%4,%5,%6,%7},{%8,%9},{%0,%1,%2,%3};"
        : "+f"(d[0]), "+f"(d[1]), "+f"(d[2]), "+f"(d[3])
        : "r"(a[0]), "r"(a[1]), "r"(a[2]), "r"(a[3]), "r"(b0), "r"(b1));
}
__device__ __forceinline__ void cp16(uint32_t dst, const void* src) {
    asm volatile("cp.async.cg.shared.global [%0], [%1], 16;"
                 :: "r"(dst), "l"(src));
}
#define CP_COMMIT() asm volatile("cp.async.commit_group;" ::: "memory")
#define CP_WAIT0()  asm volatile("cp.async.wait_group 0;" ::: "memory")

// ---------------------------------------------------------------------------
// Precompute 1: per-row W1 decomposition + per-batch base vectors
// ---------------------------------------------------------------------------
__global__ void precomp_aux(const float* __restrict__ W1,
                            const float* __restrict__ b1,
                            const float* __restrict__ z) {
    int k = threadIdx.x;
    int b = blockIdx.x;
    const float* row = W1 + k * DINn;
    float d = b1[k];
    const float* zb = z + b * LATn;
#pragma unroll 16
    for (int l = 0; l < LATn; ++l) d += row[3 + l] * zb[l];
    g_base[b * Hn + k] = d;
    if (b == 0) {
        float s = 0.f;
#pragma unroll 16
        for (int l = 0; l < LATn; ++l) s += row[3 + l];
        g_c0[k] = row[0]; g_c1[k] = row[1]; g_ct[k] = row[2]; g_csum[k] = s;
    }
}

// ---------------------------------------------------------------------------
// Precompute 2: W2 and fused divergence matrix M -> fp16, chunk-major
// ---------------------------------------------------------------------------
__global__ void precomp_w(const float* __restrict__ W1,
                          const float* __restrict__ W2,
                          const float* __restrict__ W3) {
    int j = blockIdx.x;   // 256
    int k = threadIdx.x;  // 256
    float w2 = W2[j * Hn + k];
    float mm = w2 * (W1[k * DINn] * W3[j] + W1[k * DINn + 1] * W3[Hn + j]);
    int chunk = k >> 6, kk = k & 63;
    int idx = chunk * (Hn * KCH) + j * KCH + kk;
    g_W16[idx] = __float2half_rn(w2);
    g_W16[NCHUNK * Hn * KCH + idx] = __float2half_rn(mm);
}

// ---------------------------------------------------------------------------
// SMEM layout (byte offsets)
// ---------------------------------------------------------------------------
#define SM_PK    0              // float4[256]: (c0, c1, csum, ct)    4096
#define SM_EP    4096           // float4[256]: (b2, W3_0, W3_1, 0)   4096
#define SM_BASE  8192           // 1024
#define SM_BT    9216           // 1024: base + t*ct, per step
#define SM_X0    10240          // 512
#define SM_X1    10752
#define SM_SS    11264
#define SM_PART  11776          // [3][4][128] f32 = 6144 -> 17920
#define SM_AH    17920          // 2 bufs x (128 x 72 halfs = 18432) = 36864
#define SM_B     54784          // 2 bufs x (256 x 72 halfs = 36864) = 73728
#define SM_AG    128512         // 128 x 264 halfs = 67584 (g1 full-width)
#define SM_TOTAL 196096

#define ABUF_SZ  18432
#define BBUF_SZ  36864
#define AG_STRIDE 528

// ---------------------------------------------------------------------------
// Main fused CNF kernel, 16 warps (4M x 4N warp grid, 32x64 warp tiles):
// more warps per SMSP so scalar phases (layer-1 MUFU, epilogue tanh) of some
// warps overlap MMA of others. Structure otherwise identical to the 431us
// kernel: tanh once/step, single-term velocity + single-term divergence GEMM,
// cp.async double-buffered B stream, g2 stash in registers.
// ---------------------------------------------------------------------------
__global__ void __launch_bounds__(NTHREADS, 1)
cnf_kernel(const float* __restrict__ x,
           const float* __restrict__ b2,
           const float* __restrict__ W3,
           const float* __restrict__ b3,
           const float* __restrict__ osc,
           float* __restrict__ out,
           int out_size) {
    extern __shared__ char smem[];
    float* sf = reinterpret_cast<float*>(smem);
    const uint32_t sb = smem_u32(smem);

    const int tid  = threadIdx.x;
    const int wid  = tid >> 5;
    const int lane = tid & 31;
    const int gp0  = blockIdx.x * PPC;
    const int bidx = gp0 >> 11;

    // packed constants -> smem
    if (tid < Hn) {
        reinterpret_cast<float4*>(smem + SM_PK)[tid] =
            make_float4(g_c0[tid], g_c1[tid], g_csum[tid], g_ct[tid]);
        reinterpret_cast<float4*>(smem + SM_EP)[tid] =
            make_float4(b2[tid], W3[tid], W3[Hn + tid], 0.f);
        float bsv = g_base[bidx * Hn + tid];
        sf[(SM_BASE >> 2) + tid] = bsv;
        sf[(SM_BT >> 2) + tid]   = bsv;   // step 0: t = 0
    }
    if (tid < PPC) {
        int gp = gp0 + tid;
        sf[(SM_X0 >> 2) + tid] = x[gp * 2 + 0];
        sf[(SM_X1 >> 2) + tid] = x[gp * 2 + 1];
        sf[(SM_SS >> 2) + tid] = 0.f;
    }

// issue B-tile q (q in [0,NTILES)) into buffer (q&1) via cp.async
// DATA is 256 rows x 8 uint4 = 2048 uint4 (the 9th uint4/row is ldsm padding,
// never written/read as data) -> exactly 4 rounds of 512 threads.
#define ISSUE_B(q) do {                                                    \
        int _q8 = (q) & 7;                                                 \
        int _img = (_q8 >= NCHUNK) ? 1 : 0;                                \
        int _ch  = (q) & 3;                                                \
        const __half* _src = g_W16 + (_img * NCHUNK + _ch) * (Hn * KCH);   \
        uint32_t _dst = sb + SM_B + (uint32_t)((q) & 1) * BBUF_SZ;         \
        _Pragma("unroll")                                                  \
        for (int _i = 0; _i < 4; ++_i) {                                   \
            int _idx = _i * NTHREADS + tid;                                \
            int _j = _idx >> 3, _kb = _idx & 7;                            \
            cp16(_dst + (uint32_t)_j * 144u + (uint32_t)_kb * 16u,         \
                 _src + _idx * 8);                                         \
        }                                                                  \
        CP_COMMIT();                                                       \
    } while (0)

    ISSUE_B(0);
    __syncthreads();

    const float scale = __ldg(osc);
    const float dt  = 1.0f / (float)STEPSn;
    const float b30 = __ldg(b3), b31 = __ldg(b3 + 1);

    // layer-1 mapping: 128 points x 4 k-quarters of 16
    const int p_mine = tid >> 2;
    const int kq     = tid & 3;
    // mma warp tiling: 4 (M) x 4 (N), 32x64 warp tiles
    const int warp_m = wid >> 2;
    const int warp_n = wid & 3;
    const int m0w = warp_m * 32;
    const int n0w = warp_n * 64;
    const int grp = lane >> 2, tig = lane & 3;
    const uint32_t aoff  = (uint32_t)(lane & 15) * 144u + ((uint32_t)(lane >> 4) << 4);
    const uint32_t aoffG = (uint32_t)(lane & 15) * AG_STRIDE + ((uint32_t)(lane >> 4) << 4);
    const uint32_t boff = ((uint32_t)((lane & 7) + ((lane >> 4) << 3))) * 144u
                        + (((uint32_t)(lane >> 3) & 1u) << 4);

    const float4* pk4 = reinterpret_cast<const float4*>(smem + SM_PK);
    const float4* ep4 = reinterpret_cast<const float4*>(smem + SM_EP);
    const float* bts  = sf + (SM_BT >> 2);
    float* part = sf + (SM_PART >> 2);

    uint32_t g2a[2][8], g2b[2][8];   // layer-2 derivative stash (packed half2)

#pragma unroll 1
    for (int step = 0; step < STEPSn; ++step) {
        const float px0 = sf[(SM_X0 >> 2) + p_mine];
        const float px1 = sf[(SM_X1 >> 2) + p_mine];
        const float psv = sf[(SM_SS >> 2) + p_mine];

        // layer-1 k-slice for chunk c: tanh once; h fp16 -> A buf (c&1),
        // g1 fp16 -> full-width AG at final column position.
        auto layer1 = [&](int c) {
            const int kkb = kq * 16;
            const uint32_t aw = (uint32_t)(c & 1) * ABUF_SZ;
            const float4* pkc = pk4 + c * KCH;
            const float* btc  = bts + c * KCH;
#pragma unroll
            for (int kk2 = 0; kk2 < 16; kk2 += 2) {
                int kk = kkb + kk2;
                float4 pa = pkc[kk];
                float4 pb = pkc[kk + 1];
                float2 btv = *reinterpret_cast<const float2*>(btc + kk);
                float u0 = btv.x + psv * pa.z + px0 * pa.x + px1 * pa.y;
                float u1 = btv.y + psv * pb.z + px0 * pb.x + px1 * pb.y;
                float h0 = ftanh(u0), h1 = ftanh(u1);
                uint32_t o = aw + (uint32_t)p_mine * 144u + (uint32_t)kk * 2u;
                *reinterpret_cast<__half2*>(smem + SM_AH + o) =
                    __floats2half2_rn(h0, h1);
                uint32_t og = (uint32_t)p_mine * AG_STRIDE
                            + (uint32_t)(c * KCH + kk) * 2u;
                *reinterpret_cast<__half2*>(smem + SM_AG + og) =
                    __floats2half2_rn(1.f - h0 * h0, 1.f - h1 * h1);
            }
        };

        float acc[2][8][4];
#pragma unroll
        for (int mi = 0; mi < 2; ++mi)
#pragma unroll
            for (int ni = 0; ni < 8; ++ni)
#pragma unroll
                for (int q = 0; q < 4; ++q) acc[mi][ni][q] = 0.f;

        // ============ pass 0: velocity GEMM (h . W2, single term) ==========
        layer1(0);
#pragma unroll 1
        for (int chunk = 0; chunk < NCHUNK; ++chunk) {
            const int q = step * 8 + chunk;

            CP_WAIT0();          // B(q) landed
            __syncthreads();     // A(chunk) stores + B visible; prev reads done
            ISSUE_B(q + 1);      // hide next B under MMA(q)

            const uint32_t bb = sb + SM_B + (uint32_t)(q & 1) * BBUF_SZ;
            const uint32_t ab = sb + SM_AH + (uint32_t)(chunk & 1) * ABUF_SZ;
#pragma unroll
            for (int ks = 0; ks < 4; ++ks) {
                uint32_t a[2][4];
#pragma unroll
                for (int mi = 0; mi < 2; ++mi) {
                    uint32_t ad = ab + (uint32_t)(m0w + mi * 16) * 144u
                                + (uint32_t)ks * 32u + aoff;
                    ldsm4(a[mi][0], a[mi][1], a[mi][2], a[mi][3], ad);
                }
#pragma unroll
                for (int ng = 0; ng < 4; ++ng) {
                    uint32_t r0, r1, r2, r3;
                    uint32_t bd = bb + (uint32_t)(n0w + ng * 16) * 144u
                                + (uint32_t)ks * 32u + boff;
                    ldsm4(r0, r1, r2, r3, bd);
#pragma unroll
                    for (int mi = 0; mi < 2; ++mi) {
                        mma16816(acc[mi][ng * 2],     a[mi], r0, r1);
                        mma16816(acc[mi][ng * 2 + 1], a[mi], r2, r3);
                    }
                }
            }
            // layer-1 for chunk+1 into the OTHER A buffer; published by the
            // next iteration's top barrier.
            if (chunk + 1 < NCHUNK) layer1(chunk + 1);
        }

        // ---- epilogue 0: h2, v partials; g2 -> registers ----
        {
            float v0p[4], v1p[4];
#pragma unroll
            for (int i = 0; i < 4; ++i) { v0p[i] = 0.f; v1p[i] = 0.f; }
#pragma unroll
            for (int mi = 0; mi < 2; ++mi) {
#pragma unroll
                for (int ni = 0; ni < 8; ++ni) {
                    int j0 = n0w + ni * 8 + tig * 2;
                    float* c = acc[mi][ni];
                    float4 e0 = ep4[j0];
                    float4 e1 = ep4[j0 + 1];
                    float h00 = ftanh(c[0] + e0.x);
                    float h01 = ftanh(c[1] + e1.x);
                    float h10 = ftanh(c[2] + e0.x);
                    float h11 = ftanh(c[3] + e1.x);
                    v0p[2*mi]   += e0.y * h00 + e1.y * h01;
                    v0p[2*mi+1] += e0.y * h10 + e1.y * h11;
                    v1p[2*mi]   += e0.z * h00 + e1.z * h01;
                    v1p[2*mi+1] += e0.z * h10 + e1.z * h11;
                    __half2 ga = __floats2half2_rn(1.f - h00 * h00, 1.f - h01 * h01);
                    __half2 gb = __floats2half2_rn(1.f - h10 * h10, 1.f - h11 * h11);
                    g2a[mi][ni] = *reinterpret_cast<uint32_t*>(&ga);
                    g2b[mi][ni] = *reinterpret_cast<uint32_t*>(&gb);
                }
            }
#pragma unroll
            for (int i = 0; i < 4; ++i) {
                v0p[i] += __shfl_xor_sync(0xffffffffu, v0p[i], 1);
                v0p[i] += __shfl_xor_sync(0xffffffffu, v0p[i], 2);
                v1p[i] += __shfl_xor_sync(0xffffffffu, v1p[i], 1);
                v1p[i] += __shfl_xor_sync(0xffffffffu, v1p[i], 2);
            }
            if (tig == 0) {
#pragma unroll
                for (int i = 0; i < 4; ++i) {
                    int p = m0w + (i >> 1) * 16 + grp + (i & 1) * 8;
                    part[0 * 512 + warp_n * 128 + p] = v0p[i];
                    part[1 * 512 + warp_n * 128 + p] = v1p[i];
                }
            }
        }

        // ============ pass 1: divergence GEMM (g1 . M, single term) ========
#pragma unroll
        for (int mi = 0; mi < 2; ++mi)
#pragma unroll
            for (int ni = 0; ni < 8; ++ni)
#pragma unroll
                for (int q = 0; q < 4; ++q) acc[mi][ni][q] = 0.f;

#pragma unroll 1
        for (int chunk = 0; chunk < NCHUNK; ++chunk) {
            const int q = step * 8 + 4 + chunk;

            CP_WAIT0();
            __syncthreads();
            if (q + 1 < NTILES) ISSUE_B(q + 1);

            const uint32_t bb = sb + SM_B + (uint32_t)(q & 1) * BBUF_SZ;
            const uint32_t ab = sb + SM_AG + (uint32_t)chunk * 128u;
#pragma unroll
            for (int ks = 0; ks < 4; ++ks) {
                uint32_t a[2][4];
#pragma unroll
                for (int mi = 0; mi < 2; ++mi) {
                    uint32_t ad = ab + (uint32_t)(m0w + mi * 16) * AG_STRIDE
                                + (uint32_t)ks * 32u + aoffG;
                    ldsm4(a[mi][0], a[mi][1], a[mi][2], a[mi][3], ad);
                }
#pragma unroll
                for (int ng = 0; ng < 4; ++ng) {
                    uint32_t r0, r1, r2, r3;
                    uint32_t bd = bb + (uint32_t)(n0w + ng * 16) * 144u
                                + (uint32_t)ks * 32u + boff;
                    ldsm4(r0, r1, r2, r3, bd);
#pragma unroll
                    for (int mi = 0; mi < 2; ++mi) {
                        mma16816(acc[mi][ng * 2],     a[mi], r0, r1);
                        mma16816(acc[mi][ng * 2 + 1], a[mi], r2, r3);
                    }
                }
            }
            // no bottom sync: AG is read-only; B buffers guarded by top sync
        }

        // ---- epilogue 1: dv partials from g2 registers ----
        {
            float dvp[4];
#pragma unroll
            for (int i = 0; i < 4; ++i) dvp[i] = 0.f;
#pragma unroll
            for (int mi = 0; mi < 2; ++mi) {
#pragma unroll
                for (int ni = 0; ni < 8; ++ni) {
                    float* c = acc[mi][ni];
                    float2 ga = __half22float2(
                        *reinterpret_cast<__half2*>(&g2a[mi][ni]));
                    float2 gb = __half22float2(
                        *reinterpret_cast<__half2*>(&g2b[mi][ni]));
                    dvp[2*mi]   += ga.x * c[0] + ga.y * c[1];
                    dvp[2*mi+1] += gb.x * c[2] + gb.y * c[3];
                }
            }
#pragma unroll
            for (int i = 0; i < 4; ++i) {
                dvp[i] += __shfl_xor_sync(0xffffffffu, dvp[i], 1);
                dvp[i] += __shfl_xor_sync(0xffffffffu, dvp[i], 2);
            }
            if (tig == 0) {
#pragma unroll
                for (int i = 0; i < 4; ++i) {
                    int p = m0w + (i >> 1) * 16 + grp + (i & 1) * 8;
                    part[2 * 512 + warp_n * 128 + p] = dvp[i];
                }
            }
        }
        __syncthreads();

        // ---- state update + next-step bt precompute ----
        if (tid < PPC) {
            float v0 = b30, v1 = b31, dv = 0.f;
#pragma unroll
            for (int wn = 0; wn < 4; ++wn) {
                v0 += part[0 * 512 + wn * 128 + tid];
                v1 += part[1 * 512 + wn * 128 + tid];
                dv += part[2 * 512 + wn * 128 + tid];
            }
            sf[(SM_X0 >> 2) + tid] += v0 * scale * dt;
            sf[(SM_X1 >> 2) + tid] += v1 * scale * dt;
            sf[(SM_SS >> 2) + tid] += dv * scale * dt;
        }
        if (step + 1 < STEPSn && tid < Hn) {
            float tn = dt * (float)(step + 1);
            sf[(SM_BT >> 2) + tid] = sf[(SM_BASE >> 2) + tid] + tn * pk4[tid].w;
        }
        __syncthreads();
    }

    if (tid < PPC) {
        int gp = gp0 + tid;
        out[gp * 2 + 0] = sf[(SM_X0 >> 2) + tid];
        out[gp * 2 + 1] = sf[(SM_X1 >> 2) + tid];
        if (out_size >= NPTS * PDn + NPTS)
            out[NPTS * PDn + gp] = sf[(SM_SS >> 2) + tid];
    }
#undef ISSUE_B
}

// ---------------------------------------------------------------------------
// kernel_launch
// Inputs (metadata order): x, z, W1, b1, W2, b2, W3, b3, out_scale
// ---------------------------------------------------------------------------
extern "C" void kernel_launch(void* const* d_in, const int* in_sizes, int n_in,
                              void* d_out, int out_size) {
    const float* x   = (const float*)d_in[0];
    const float* z   = (const float*)d_in[1];
    const float* W1  = (const float*)d_in[2];
    const float* b1  = (const float*)d_in[3];
    const float* W2  = (const float*)d_in[4];
    const float* b2  = (const float*)d_in[5];
    const float* W3  = (const float*)d_in[6];
    const float* b3  = (const float*)d_in[7];
    const float* osc = (const float*)d_in[8];
    float* out = (float*)d_out;

    precomp_aux<<<Bn, 256>>>(W1, b1, z);
    precomp_w<<<256, 256>>>(W1, W2, W3);

    cudaFuncSetAttribute(cnf_kernel, cudaFuncAttributeMaxDynamicSharedMemorySize,
                         SM_TOTAL);
    cnf_kernel<<<NCTA, NTHREADS, SM_TOTAL>>>(x, b2, W3, b3, osc, out, out_size);
}

// round 15
// speedup vs baseline: 1.2519x; 1.2519x over previous
#include <cuda_runtime.h>
#include <cuda_fp16.h>
#include <cstdint>

// ---------------------------------------------------------------------------
// Problem constants
// ---------------------------------------------------------------------------
#define Bn     32
#define Nn     2048
#define PDn    2
#define LATn   128
#define Hn     256
#define STEPSn 5
#define DINn   131
#define NPTS   (Bn * Nn)         // 65536
#define PPC    128               // points per CTA (= GEMM M)
#define NCTA   (NPTS / PPC)      // 512
#define KCH    64                // K-chunk
#define NCHUNK (Hn / KCH)        // 4
#define NTHREADS 256
#define NTILES (STEPSn * 2 * NCHUNK)   // 40 B-tiles over the whole kernel

// ---------------------------------------------------------------------------
// Device globals
// ---------------------------------------------------------------------------
// fp16 weights, chunk-major: [matrix(2: W2, M)][chunk(4)][j=256][kk=64]
__device__ __align__(16) __half g_W16[2 * NCHUNK * Hn * KCH];
__device__ __align__(16) float g_base[Bn * Hn];
__device__ __align__(16) float g_c0[Hn], g_c1[Hn], g_ct[Hn], g_csum[Hn];

// Batched tanh: 4 tanh sharing one reciprocal (5 MUFU instead of 8).
// Clamp at +/-9: tanh(9) = 1 - 3e-8 (exact to fp32), and d^4 <= 2e31 (no ovf).
__device__ __forceinline__ void ftanh4(const float* u, float* h) {
    float e0 = __expf(2.0f * fminf(fmaxf(u[0], -9.f), 9.f));
    float e1 = __expf(2.0f * fminf(fmaxf(u[1], -9.f), 9.f));
    float e2 = __expf(2.0f * fminf(fmaxf(u[2], -9.f), 9.f));
    float e3 = __expf(2.0f * fminf(fmaxf(u[3], -9.f), 9.f));
    float d0 = e0 + 1.f, d1 = e1 + 1.f, d2 = e2 + 1.f, d3 = e3 + 1.f;
    float p01 = d0 * d1, p23 = d2 * d3;
    float r = __fdividef(1.0f, p01 * p23);
    float r01 = r * p23, r23 = r * p01;
    h[0] = fmaf(-2.0f, r01 * d1, 1.0f);
    h[1] = fmaf(-2.0f, r01 * d0, 1.0f);
    h[2] = fmaf(-2.0f, r23 * d3, 1.0f);
    h[3] = fmaf(-2.0f, r23 * d2, 1.0f);
}
__device__ __forceinline__ float ftanh(float x) {
    float e = __expf(2.0f * x);
    return 1.0f - __fdividef(2.0f, e + 1.0f);
}
__device__ __forceinline__ uint32_t smem_u32(const void* p) {
    uint32_t a;
    asm("{ .reg .u64 t; cvta.to.shared.u64 t, %1; cvt.u32.u64 %0, t; }"
        : "=r"(a) : "l"(p));
    return a;
}
__device__ __forceinline__ void ldsm4(uint32_t& r0, uint32_t& r1,
                                      uint32_t& r2, uint32_t& r3, uint32_t addr) {
    asm volatile("ldmatrix.sync.aligned.m8n8.x4.shared.b16 {%0,%1,%2,%3}, [%4];"
                 : "=r"(r0), "=r"(r1), "=r"(r2), "=r"(r3) : "r"(addr));
}
__device__ __forceinline__ void mma16816(float* d, const uint32_t* a,
                                         uint32_t b0, uint32_t b1) {
    asm volatile(
        "mma.sync.aligned.m16n8k16.row.col.f32.f16.f16.f32 "
        "{%0,%1,%2,%3},{%4,%5,%6,%7},{%8,%9},{%0,%1,%2,%3};"
        : "+f"(d[0]), "+f"(d[1]), "+f"(d[2]), "+f"(d[3])
        : "r"(a[0]), "r"(a[1]), "r"(a[2]), "r"(a[3]), "r"(b0), "r"(b1));
}
__device__ __forceinline__ void cp16(uint32_t dst, const void* src) {
    asm volatile("cp.async.cg.shared.global [%0], [%1], 16;"
                 :: "r"(dst), "l"(src));
}
#define CP_COMMIT() asm volatile("cp.async.commit_group;" ::: "memory")
#define CP_WAIT0()  asm volatile("cp.async.wait_group 0;" ::: "memory")

// ---------------------------------------------------------------------------
// Precompute 1: per-row W1 decomposition + per-batch base vectors
// ---------------------------------------------------------------------------
__global__ void precomp_aux(const float* __restrict__ W1,
                            const float* __restrict__ b1,
                            const float* __restrict__ z) {
    int k = threadIdx.x;
    int b = blockIdx.x;
    const float* row = W1 + k * DINn;
    float d = b1[k];
    const float* zb = z + b * LATn;
#pragma unroll 16
    for (int l = 0; l < LATn; ++l) d += row[3 + l] * zb[l];
    g_base[b * Hn + k] = d;
    if (b == 0) {
        float s = 0.f;
#pragma unroll 16
        for (int l = 0; l < LATn; ++l) s += row[3 + l];
        g_c0[k] = row[0]; g_c1[k] = row[1]; g_ct[k] = row[2]; g_csum[k] = s;
    }
}

// ---------------------------------------------------------------------------
// Precompute 2: W2 and fused divergence matrix M -> fp16, chunk-major
// ---------------------------------------------------------------------------
__global__ void precomp_w(const float* __restrict__ W1,
                          const float* __restrict__ W2,
                          const float* __restrict__ W3) {
    int j = blockIdx.x;   // 256
    int k = threadIdx.x;  // 256
    float w2 = W2[j * Hn + k];
    float mm = w2 * (W1[k * DINn] * W3[j] + W1[k * DINn + 1] * W3[Hn + j]);
    int chunk = k >> 6, kk = k & 63;
    int idx = chunk * (Hn * KCH) + j * KCH + kk;
    g_W16[idx] = __float2half_rn(w2);
    g_W16[NCHUNK * Hn * KCH + idx] = __float2half_rn(mm);
}

// ---------------------------------------------------------------------------
// SMEM layout (byte offsets) — identical to the 431us kernel
// ---------------------------------------------------------------------------
#define SM_C0    0
#define SM_C1    1024
#define SM_CT    2048
#define SM_CS    3072
#define SM_BASE  4096
#define SM_B2    5120
#define SM_W30   6144
#define SM_W31   7168
#define SM_X0    8192
#define SM_X1    8704
#define SM_SS    9216
#define SM_PART  9728          // [3][4][128] f32 = 6144
#define SM_AHI   16384         // 2 bufs x (128 x 72 halfs = 18432) = 36864
#define SM_B     53248         // 2 bufs x (256 x 72 halfs = 36864) = 73728
#define SM_AG    126976        // 128 x 264 halfs = 67584 (g1 full-width)
#define SM_TOTAL 194560

#define ABUF_SZ  18432
#define BBUF_SZ  36864
#define AG_STRIDE 528

// ---------------------------------------------------------------------------
// Main fused CNF kernel (R11 structure + batched-reciprocal tanh):
// tanh ONCE per step; pass0 = velocity GEMM single term with A ping-pong;
// pass1 = divergence GEMM single term reading full-width g1; g2 in registers.
// ---------------------------------------------------------------------------
__global__ void __launch_bounds__(NTHREADS, 1)
cnf_kernel(const float* __restrict__ x,
           const float* __restrict__ b2,
           const float* __restrict__ W3,
           const float* __restrict__ b3,
           const float* __restrict__ osc,
           float* __restrict__ out,
           int out_size) {
    extern __shared__ char smem[];
    float* sf = reinterpret_cast<float*>(smem);
    const uint32_t sb = smem_u32(smem);

    const int tid  = threadIdx.x;
    const int wid  = tid >> 5;
    const int lane = tid & 31;
    const int gp0  = blockIdx.x * PPC;
    const int bidx = gp0 >> 11;

    // load constants into smem
    sf[(SM_C0 >> 2) + tid]   = g_c0[tid];
    sf[(SM_C1 >> 2) + tid]   = g_c1[tid];
    sf[(SM_CT >> 2) + tid]   = g_ct[tid];
    sf[(SM_CS >> 2) + tid]   = g_csum[tid];
    sf[(SM_BASE >> 2) + tid] = g_base[bidx * Hn + tid];
    sf[(SM_B2 >> 2) + tid]   = b2[tid];
    sf[(SM_W30 >> 2) + tid]  = W3[tid];
    sf[(SM_W31 >> 2) + tid]  = W3[Hn + tid];
    if (tid < PPC) {
        int gp = gp0 + tid;
        sf[(SM_X0 >> 2) + tid] = x[gp * 2 + 0];
        sf[(SM_X1 >> 2) + tid] = x[gp * 2 + 1];
        sf[(SM_SS >> 2) + tid] = 0.f;
    }

// issue B-tile q (q in [0,NTILES)) into buffer (q&1) via cp.async
#define ISSUE_B(q) do {                                                    \
        int _q8 = (q) & 7;                                                 \
        int _img = (_q8 >= NCHUNK) ? 1 : 0;                                \
        int _ch  = (q) & 3;                                                \
        const __half* _src = g_W16 + (_img * NCHUNK + _ch) * (Hn * KCH);   \
        uint32_t _dst = sb + SM_B + (uint32_t)((q) & 1) * BBUF_SZ;         \
        _Pragma("unroll")                                                  \
        for (int _i = 0; _i < 8; ++_i) {                                   \
            int _idx = _i * NTHREADS + tid;                                \
            int _j = _idx >> 3, _kb = _idx & 7;                            \
            cp16(_dst + (uint32_t)_j * 144u + (uint32_t)_kb * 16u,         \
                 _src + _idx * 8);                                         \
        }                                                                  \
        CP_COMMIT();                                                       \
    } while (0)

    ISSUE_B(0);
    __syncthreads();

    const float scale = __ldg(osc);
    const float dt  = 1.0f / (float)STEPSn;
    const float b30 = __ldg(b3), b31 = __ldg(b3 + 1);

    // layer-1 mapping
    const int p_mine = tid >> 1;
    const int khalf  = tid & 1;
    // mma warp tiling: 2 (M) x 4 (N), 64x64 warp tiles
    const int warp_m = wid >> 2;
    const int warp_n = wid & 3;
    const int m0w = warp_m * 64;
    const int n0w = warp_n * 64;
    const int grp = lane >> 2, tig = lane & 3;
    const uint32_t aoff  = (uint32_t)(lane & 15) * 144u + ((uint32_t)(lane >> 4) << 4);
    const uint32_t aoffG = (uint32_t)(lane & 15) * AG_STRIDE + ((uint32_t)(lane >> 4) << 4);
    const uint32_t boff = ((uint32_t)((lane & 7) + ((lane >> 4) << 3))) * 144u
                        + (((uint32_t)(lane >> 3) & 1u) << 4);

    const float* c0s = sf + (SM_C0 >> 2);
    const float* c1s = sf + (SM_C1 >> 2);
    const float* cts = sf + (SM_CT >> 2);
    const float* css = sf + (SM_CS >> 2);
    const float* bas = sf + (SM_BASE >> 2);
    const float* b2s = sf + (SM_B2 >> 2);
    const float* w30s = sf + (SM_W30 >> 2);
    const float* w31s = sf + (SM_W31 >> 2);
    float* part = sf + (SM_PART >> 2);

    uint32_t g2a[4][8], g2b[4][8];   // layer-2 derivative stash (packed half2)

#pragma unroll 1
    for (int step = 0; step < STEPSn; ++step) {
        const float tcur = dt * (float)step;
        const float px0 = sf[(SM_X0 >> 2) + p_mine];
        const float px1 = sf[(SM_X1 >> 2) + p_mine];
        const float psv = sf[(SM_SS >> 2) + p_mine];

        // layer-1 k-slice for chunk c: batched tanh; h fp16 -> A buf (c&1),
        // g1 fp16 -> full-width AG at final column position.
        auto layer1 = [&](int c) {
            const int kkb = khalf * 32;
            const uint32_t aw = (uint32_t)(c & 1) * ABUF_SZ;
#pragma unroll
            for (int kk2 = 0; kk2 < 32; kk2 += 4) {
                int kk = kkb + kk2;
                int k = c * KCH + kk;
                float u[4], h[4];
#pragma unroll
                for (int t2 = 0; t2 < 4; ++t2) {
                    int kt = k + t2;
                    u[t2] = bas[kt] + tcur * cts[kt] + psv * css[kt]
                          + px0 * c0s[kt] + px1 * c1s[kt];
                }
                ftanh4(u, h);
                uint32_t o = aw + (uint32_t)p_mine * 144u + (uint32_t)kk * 2u;
                *reinterpret_cast<__half2*>(smem + SM_AHI + o) =
                    __floats2half2_rn(h[0], h[1]);
                *reinterpret_cast<__half2*>(smem + SM_AHI + o + 4u) =
                    __floats2half2_rn(h[2], h[3]);
                uint32_t og = (uint32_t)p_mine * AG_STRIDE + (uint32_t)k * 2u;
                *reinterpret_cast<__half2*>(smem + SM_AG + og) =
                    __floats2half2_rn(1.f - h[0] * h[0], 1.f - h[1] * h[1]);
                *reinterpret_cast<__half2*>(smem + SM_AG + og + 4u) =
                    __floats2half2_rn(1.f - h[2] * h[2], 1.f - h[3] * h[3]);
            }
        };

        float acc[4][8][4];
#pragma unroll
        for (int mi = 0; mi < 4; ++mi)
#pragma unroll
            for (int ni = 0; ni < 8; ++ni)
#pragma unroll
                for (int q = 0; q < 4; ++q) acc[mi][ni][q] = 0.f;

        // ============ pass 0: velocity GEMM (h . W2, single term) ==========
        layer1(0);
#pragma unroll 1
        for (int chunk = 0; chunk < NCHUNK; ++chunk) {
            const int q = step * 8 + chunk;

            CP_WAIT0();          // B(q) landed
            __syncthreads();     // A(chunk) stores + B visible; prev reads done
            ISSUE_B(q + 1);      // hide next B under MMA(q)

            const uint32_t bb = sb + SM_B + (uint32_t)(q & 1) * BBUF_SZ;
            const uint32_t ab = sb + SM_AHI + (uint32_t)(chunk & 1) * ABUF_SZ;
#pragma unroll
            for (int ks = 0; ks < 4; ++ks) {
                uint32_t a[4][4];
#pragma unroll
                for (int mi = 0; mi < 4; ++mi) {
                    uint32_t ad = ab + (uint32_t)(m0w + mi * 16) * 144u
                                + (uint32_t)ks * 32u + aoff;
                    ldsm4(a[mi][0], a[mi][1], a[mi][2], a[mi][3], ad);
                }
#pragma unroll
                for (int ng = 0; ng < 4; ++ng) {
                    uint32_t r0, r1, r2, r3;
                    uint32_t bd = bb + (uint32_t)(n0w + ng * 16) * 144u
                                + (uint32_t)ks * 32u + boff;
                    ldsm4(r0, r1, r2, r3, bd);
#pragma unroll
                    for (int mi = 0; mi < 4; ++mi) {
                        mma16816(acc[mi][ng * 2],     a[mi], r0, r1);
                        mma16816(acc[mi][ng * 2 + 1], a[mi], r2, r3);
                    }
                }
            }
            // layer-1 for chunk+1 into the OTHER A buffer; published by the
            // next iteration's top barrier.
            if (chunk + 1 < NCHUNK) layer1(chunk + 1);
        }

        // ---- epilogue 0: h2, v partials; g2 -> registers ----
        {
            float v0p[8], v1p[8];
#pragma unroll
            for (int i = 0; i < 8; ++i) { v0p[i] = 0.f; v1p[i] = 0.f; }
#pragma unroll
            for (int mi = 0; mi < 4; ++mi) {
#pragma unroll
                for (int ni = 0; ni < 8; ++ni) {
                    int j0 = n0w + ni * 8 + tig * 2;
                    float* c = acc[mi][ni];
                    float bj0 = b2s[j0], bj1 = b2s[j0 + 1];
                    float u[4] = {c[0] + bj0, c[1] + bj1, c[2] + bj0, c[3] + bj1};
                    float h[4];
                    ftanh4(u, h);
                    float w300 = w30s[j0], w301 = w30s[j0 + 1];
                    float w310 = w31s[j0], w311 = w31s[j0 + 1];
                    v0p[2*mi]   += w300 * h[0] + w301 * h[1];
                    v0p[2*mi+1] += w300 * h[2] + w301 * h[3];
                    v1p[2*mi]   += w310 * h[0] + w311 * h[1];
                    v1p[2*mi+1] += w310 * h[2] + w311 * h[3];
                    __half2 ga = __floats2half2_rn(1.f - h[0] * h[0], 1.f - h[1] * h[1]);
                    __half2 gb = __floats2half2_rn(1.f - h[2] * h[2], 1.f - h[3] * h[3]);
                    g2a[mi][ni] = *reinterpret_cast<uint32_t*>(&ga);
                    g2b[mi][ni] = *reinterpret_cast<uint32_t*>(&gb);
                }
            }
#pragma unroll
            for (int i = 0; i < 8; ++i) {
                v0p[i] += __shfl_xor_sync(0xffffffffu, v0p[i], 1);
                v0p[i] += __shfl_xor_sync(0xffffffffu, v0p[i], 2);
                v1p[i] += __shfl_xor_sync(0xffffffffu, v1p[i], 1);
                v1p[i] += __shfl_xor_sync(0xffffffffu, v1p[i], 2);
            }
            if (tig == 0) {
#pragma unroll
                for (int i = 0; i < 8; ++i) {
                    int p = m0w + (i >> 1) * 16 + grp + (i & 1) * 8;
                    part[0 * 512 + warp_n * 128 + p] = v0p[i];
                    part[1 * 512 + warp_n * 128 + p] = v1p[i];
                }
            }
        }

        // ============ pass 1: divergence GEMM (g1 . M, single term) ========
#pragma unroll
        for (int mi = 0; mi < 4; ++mi)
#pragma unroll
            for (int ni = 0; ni < 8; ++ni)
#pragma unroll
                for (int q = 0; q < 4; ++q) acc[mi][ni][q] = 0.f;

#pragma unroll 1
        for (int chunk = 0; chunk < NCHUNK; ++chunk) {
            const int q = step * 8 + 4 + chunk;

            CP_WAIT0();
            __syncthreads();
            if (q + 1 < NTILES) ISSUE_B(q + 1);

            const uint32_t bb = sb + SM_B + (uint32_t)(q & 1) * BBUF_SZ;
            const uint32_t ab = sb + SM_AG + (uint32_t)chunk * 128u;
#pragma unroll
            for (int ks = 0; ks < 4; ++ks) {
                uint32_t a[4][4];
#pragma unroll
                for (int mi = 0; mi < 4; ++mi) {
                    uint32_t ad = ab + (uint32_t)(m0w + mi * 16) * AG_STRIDE
                                + (uint32_t)ks * 32u + aoffG;
                    ldsm4(a[mi][0], a[mi][1], a[mi][2], a[mi][3], ad);
                }
#pragma unroll
                for (int ng = 0; ng < 4; ++ng) {
                    uint32_t r0, r1, r2, r3;
                    uint32_t bd = bb + (uint32_t)(n0w + ng * 16) * 144u
                                + (uint32_t)ks * 32u + boff;
                    ldsm4(r0, r1, r2, r3, bd);
#pragma unroll
                    for (int mi = 0; mi < 4; ++mi) {
                        mma16816(acc[mi][ng * 2],     a[mi], r0, r1);
                        mma16816(acc[mi][ng * 2 + 1], a[mi], r2, r3);
                    }
                }
            }
            // no bottom sync: AG is read-only; B buffers guarded by top sync
        }

        // ---- epilogue 1: dv partials from g2 registers ----
        {
            float dvp[8];
#pragma unroll
            for (int i = 0; i < 8; ++i) dvp[i] = 0.f;
#pragma unroll
            for (int mi = 0; mi < 4; ++mi) {
#pragma unroll
                for (int ni = 0; ni < 8; ++ni) {
                    float* c = acc[mi][ni];
                    float2 ga = __half22float2(
                        *reinterpret_cast<__half2*>(&g2a[mi][ni]));
                    float2 gb = __half22float2(
                        *reinterpret_cast<__half2*>(&g2b[mi][ni]));
                    dvp[2*mi]   += ga.x * c[0] + ga.y * c[1];
                    dvp[2*mi+1] += gb.x * c[2] + gb.y * c[3];
                }
            }
#pragma unroll
            for (int i = 0; i < 8; ++i) {
                dvp[i] += __shfl_xor_sync(0xffffffffu, dvp[i], 1);
                dvp[i] += __shfl_xor_sync(0xffffffffu, dvp[i], 2);
            }
            if (tig == 0) {
#pragma unroll
                for (int i = 0; i < 8; ++i) {
                    int p = m0w + (i >> 1) * 16 + grp + (i & 1) * 8;
                    part[2 * 512 + warp_n * 128 + p] = dvp[i];
                }
            }
        }
        __syncthreads();

        // ---- state update ----
        if (tid < PPC) {
            float v0 = b30, v1 = b31, dv = 0.f;
#pragma unroll
            for (int wn = 0; wn < 4; ++wn) {
                v0 += part[0 * 512 + wn * 128 + tid];
                v1 += part[1 * 512 + wn * 128 + tid];
                dv += part[2 * 512 + wn * 128 + tid];
            }
            sf[(SM_X0 >> 2) + tid] += v0 * scale * dt;
            sf[(SM_X1 >> 2) + tid] += v1 * scale * dt;
            sf[(SM_SS >> 2) + tid] += dv * scale * dt;
        }
        __syncthreads();
    }

    if (tid < PPC) {
        int gp = gp0 + tid;
        out[gp * 2 + 0] = sf[(SM_X0 >> 2) + tid];
        out[gp * 2 + 1] = sf[(SM_X1 >> 2) + tid];
        if (out_size >= NPTS * PDn + NPTS)
            out[NPTS * PDn + gp] = sf[(SM_SS >> 2) + tid];
    }
#undef ISSUE_B
}

// ---------------------------------------------------------------------------
// kernel_launch
// Inputs (metadata order): x, z, W1, b1, W2, b2, W3, b3, out_scale
// ---------------------------------------------------------------------------
extern "C" void kernel_launch(void* const* d_in, const int* in_sizes, int n_in,
                              void* d_out, int out_size) {
    const float* x   = (const float*)d_in[0];
    const float* z   = (const float*)d_in[1];
    const float* W1  = (const float*)d_in[2];
    const float* b1  = (const float*)d_in[3];
    const float* W2  = (const float*)d_in[4];
    const float* b2  = (const float*)d_in[5];
    const float* W3  = (const float*)d_in[6];
    const float* b3  = (const float*)d_in[7];
    const float* osc = (const float*)d_in[8];
    float* out = (float*)d_out;

    precomp_aux<<<Bn, 256>>>(W1, b1, z);
    precomp_w<<<256, 256>>>(W1, W2, W3);

    cudaFuncSetAttribute(cnf_kernel, cudaFuncAttributeMaxDynamicSharedMemorySize,
                         SM_TOTAL);
    cnf_kernel<<<NCTA, NTHREADS, SM_TOTAL>>>(x, b2, W3, b3, osc, out, out_size);
}